// round 17
// baseline (speedup 1.0000x reference)
#include <cuda_runtime.h>
#include <cuda_fp16.h>
#include <cuda_bf16.h>

// Problem constants
#define Bn 4
#define Cn 64
#define Hn 96
#define Wn 96
#define PLANE (Hn*Wn)            // 9216
#define NPLANES (Bn*Cn)          // 256
#define NTOT (NPLANES*PLANE)     // 2359296
#define CNT_PER_CH (Bn*PLANE)    // 36864
#define BN_EPS 1e-5f
#define NPART 36                 // partial sums per channel
#define GRIDF 576                // 64 channels x 9 tile positions; single wave

// Scratch (__device__ globals; allocation-free rule)
__device__ float    g_psum[Cn * NPART];
__device__ float    g_psq [Cn * NPART];
__device__ float    g_scl [Cn];
__device__ float    g_sh  [Cn];
__device__ unsigned g_cnt [Cn];    // per-channel arrival counter (self-reset)
__device__ unsigned g_done[Cn];    // monotone completion sequence

__device__ __forceinline__ float silu_f(float x) {
    return __fdividef(x, 1.0f + __expf(-x));
}

// Prefetch one plane-tile's 34x34 halo into registers (5 elems/thread).
__device__ __forceinline__ void prefetch_tile(const float* __restrict__ x,
                                              int plane, int ty0, int tx0,
                                              int tid, float* pre) {
    const float* xp = x + plane * PLANE;
    #pragma unroll
    for (int j = 0; j < 5; j++) {
        const int i = tid + j * 256;
        float v = 0.0f;
        if (i < 1156) {
            int hy = i / 34, hx = i % 34;
            int gy = ty0 + hy - 1, gx = tx0 + hx - 1;
            if (gy >= 0 && gy < Hn && gx >= 0 && gx < Wn) v = xp[gy * Wn + gx];
        }
        pre[j] = v;
    }
}

// ---------------------------------------------------------------------------
// Single fused kernel, channel-grouped: block (c, j) computes tile position j
// of channel c for all 4 batches.  After publishing its 4 partials it waits
// only for its 8 SIBLING blocks (same channel, all co-resident in wave 1),
// then applies BN + ReLU from smem-resident y.
// ---------------------------------------------------------------------------
__global__ __launch_bounds__(256, 4)
void kan_fused_kernel(const float* __restrict__ x,
                      const float* __restrict__ base_weight,    // (9)
                      const float* __restrict__ spline_weight,  // (9,8)
                      const float* __restrict__ spline_scaler,  // (9)
                      const float* __restrict__ gamma,
                      const float* __restrict__ beta,
                      float* __restrict__ out)
{
    __shared__ __align__(16) float s_y[Bn][1024];    // y tiles (live across wait)
    __shared__ unsigned s_t[34 * 35];                // packed (mo<<16 | u16)
    __shared__ uint2    s_coef[12 * 9];              // half2(c0,c1), half2(c2,c3)
    __shared__ float    s_rs[8], s_rq[8];
    __shared__ float    s_scl, s_sh;
    __shared__ unsigned s_e0;

    const int tid = threadIdx.x;
    const int bid = blockIdx.x;
    const int c   = bid / 9;               // channel
    const int j   = bid % 9;               // tile position within plane
    const int ty0 = (j / 3) * 32;
    const int tx0 = (j % 3) * 32;
    const int tx  = tid & 31;
    const int tyb = tid >> 5;

    // snapshot completion sequence BEFORE publishing (safe: our own arrival
    // is required for the signal, and it happens after this read)
    if (tid == 0) s_e0 = *(volatile unsigned*)&g_done[c];

    // ---- prefetch batch-0 tile while building the coefficient table ----
    float pre[5];
    prefetch_tile(x, c, ty0, tx0, tid, pre);

    // ---- coef table: uniform cubic B-spline + Hermite-folded silu base.
    //      Sentinel row m=11: tile stores w=(silu+1)/8, poly(w)=bw*(8w-1).
    if (tid < 108) {
        const int m = tid / 9, k = tid % 9;
        const float bwk = base_weight[k];
        float c0, c1, c2, c3;
        if (m < 11) {
            c0 = c1 = c2 = c3 = 0.f;
            const float F[4][4] = {
                {1.f, -3.f,  3.f, -1.f},
                {4.f,  0.f, -6.f,  3.f},
                {1.f,  3.f,  3.f, -3.f},
                {0.f,  0.f,  0.f,  1.f}
            };
            const float sc = spline_scaler[k] * (1.0f / 6.0f);
            #pragma unroll
            for (int r = 0; r < 4; r++) {
                int jj = m - 3 + r;
                if (jj >= 0 && jj < 8) {
                    float w = spline_weight[k * 8 + jj] * sc;
                    c0 += w * F[r][0]; c1 += w * F[r][1];
                    c2 += w * F[r][2]; c3 += w * F[r][3];
                }
            }
            const float x0 = -2.2f + 0.4f * (float)m;
            const float x1 = x0 + 0.4f;
            const float f0 = silu_f(x0), f1 = silu_f(x1);
            const float sg0 = 1.0f / (1.0f + __expf(-x0));
            const float sg1 = 1.0f / (1.0f + __expf(-x1));
            const float d0 = 0.4f * sg0 * (1.0f + x0 * (1.0f - sg0));
            const float d1 = 0.4f * sg1 * (1.0f + x1 * (1.0f - sg1));
            c0 += bwk * f0;
            c1 += bwk * d0;
            c2 += bwk * (3.0f * (f1 - f0) - 2.0f * d0 - d1);
            c3 += bwk * (2.0f * (f0 - f1) + d0 + d1);
        } else {
            c0 = -bwk; c1 = 8.0f * bwk; c2 = 0.f; c3 = 0.f;
        }
        __half2 h01 = __floats2half2_rn(c0, c1);
        __half2 h23 = __floats2half2_rn(c2, c3);
        uint2 w;
        w.x = *reinterpret_cast<unsigned*>(&h01);
        w.y = *reinterpret_cast<unsigned*>(&h23);
        s_coef[m * 9 + k] = w;
    }

    const char* cbase = (const char*)s_coef;

    // ================= conv over the 4 batches of this channel ==============
    #pragma unroll
    for (int it = 0; it < Bn; it++) {
        // transform prefetched regs -> packed s_t
        #pragma unroll
        for (int jj = 0; jj < 5; jj++) {
            const int i = tid + jj * 256;
            if (i < 1156) {
                float v  = pre[jj];
                float mu = (v + 2.2f) * 2.5f;
                unsigned w;
                if (mu >= 0.0f && mu < 11.0f) {
                    int m = (int)mu;
                    unsigned u16 = (unsigned)((mu - (float)m) * 65536.0f);
                    w = ((unsigned)(m * 72) << 16) | (u16 & 0xFFFFu);
                } else {
                    float s = silu_f(v);
                    unsigned u16 = (unsigned)((s + 1.0f) * (65536.0f / 8.0f));
                    if (u16 > 65535u) u16 = 65535u;
                    w = (792u << 16) | u16;           // row 11
                }
                s_t[(i / 34) * 35 + (i % 34)] = w;
            }
        }
        __syncthreads();

        // prefetch next batch's tile (latency hidden by compute below)
        if (it < Bn - 1) prefetch_tile(x, (it + 1) * Cn + c, ty0, tx0, tid, pre);

        // compute this tile (4 strided rows per thread)
        float lsum = 0.f, lsq = 0.f;
        #pragma unroll
        for (int r = 0; r < 4; r++) {
            const int oy = tyb + r * 8;
            float acc = 0.f;
            #pragma unroll
            for (int dy = 0; dy < 3; dy++) {
                #pragma unroll
                for (int dx = 0; dx < 3; dx++) {
                    const int k = dy * 3 + dx;
                    unsigned w = s_t[(oy + dy) * 35 + (tx + dx)];
                    float u = (float)(w & 0xFFFFu) * (1.0f / 65536.0f);
                    uint2 cw = *(const uint2*)(cbase + (w >> 16) + k * 8);
                    float2 c01 = __half22float2(*reinterpret_cast<__half2*>(&cw.x));
                    float2 c23 = __half22float2(*reinterpret_cast<__half2*>(&cw.y));
                    acc += fmaf(u, fmaf(u, fmaf(u, c23.y, c23.x), c01.y), c01.x);
                }
            }
            s_y[it][oy * 32 + tx] = acc;
            lsum += acc;
            lsq  = fmaf(acc, acc, lsq);
        }

        // per-tile block reduction -> race-free partial slot
        #pragma unroll
        for (int o = 16; o > 0; o >>= 1) {
            lsum += __shfl_down_sync(0xffffffffu, lsum, o);
            lsq  += __shfl_down_sync(0xffffffffu, lsq,  o);
        }
        if (tx == 0) { s_rs[tyb] = lsum; s_rq[tyb] = lsq; }
        __syncthreads();
        if (tid == 0) {
            float s = 0.f, q = 0.f;
            #pragma unroll
            for (int i = 0; i < 8; i++) { s += s_rs[i]; q += s_rq[i]; }
            g_psum[c * NPART + it * 9 + j] = s;
            g_psq [c * NPART + it * 9 + j] = q;
        }
    }

    // ============== channel-scoped completion (9 sibling blocks) ============
    __syncthreads();
    if (tid == 0) {
        __threadfence();                              // publish our 4 partials
        unsigned old = atomicAdd(&g_cnt[c], 1u);
        if (old == 8u) {                              // 9th arrival
            atomicExch(&g_cnt[c], 0u);                // reset for next replay
            float ts = 0.f, tq = 0.f;
            #pragma unroll 4
            for (int i = 0; i < NPART; i++) {
                ts += __ldcg(&g_psum[c * NPART + i]);
                tq += __ldcg(&g_psq [c * NPART + i]);
            }
            const float invN = 1.0f / (float)CNT_PER_CH;
            float mean = ts * invN;
            float var  = tq * invN - mean * mean;
            float scl  = rsqrtf(var + BN_EPS) * gamma[c];
            g_scl[c] = scl;
            g_sh [c] = fmaf(-mean, scl, beta[c]);
            __threadfence();
            atomicAdd(&g_done[c], 1u);                // signal (monotone)
        }
        const unsigned e0 = s_e0;
        while (*(volatile unsigned*)&g_done[c] == e0) __nanosleep(32);
        __threadfence();
        s_scl = *(volatile float*)&g_scl[c];
        s_sh  = *(volatile float*)&g_sh [c];
    }
    __syncthreads();

    // ================== apply BN + ReLU from smem, store ====================
    const float scl = s_scl, sh = s_sh;
    const int row  = tid >> 3;
    const int col4 = (tid & 7) * 4;
    #pragma unroll
    for (int it = 0; it < Bn; it++) {
        const int plane = it * Cn + c;
        float4 v = *reinterpret_cast<const float4*>(&s_y[it][row * 32 + col4]);
        float4 o;
        o.x = fmaxf(fmaf(v.x, scl, sh), 0.0f);
        o.y = fmaxf(fmaf(v.y, scl, sh), 0.0f);
        o.z = fmaxf(fmaf(v.z, scl, sh), 0.0f);
        o.w = fmaxf(fmaf(v.w, scl, sh), 0.0f);
        *reinterpret_cast<float4*>(&out[plane * PLANE + (ty0 + row) * Wn + tx0 + col4]) = o;
    }
}

// ---------------------------------------------------------------------------
extern "C" void kernel_launch(void* const* d_in, const int* in_sizes, int n_in,
                              void* d_out, int out_size)
{
    const float* x             = (const float*)d_in[0];
    const float* base_weight   = (const float*)d_in[1];
    const float* spline_weight = (const float*)d_in[2];
    const float* spline_scaler = (const float*)d_in[3];
    const float* bn_gamma      = (const float*)d_in[4];
    const float* bn_beta       = (const float*)d_in[5];
    float* out                 = (float*)d_out;

    kan_fused_kernel<<<GRIDF, 256>>>(x, base_weight, spline_weight, spline_scaler,
                                     bn_gamma, bn_beta, out);
}